// round 4
// baseline (speedup 1.0000x reference)
#include <cuda_runtime.h>
#include <cuda_bf16.h>

#define NB 64      // batch
#define TT 512     // timesteps
#define DD 512     // input size
#define HH 512     // hidden size

#define GROUPS 4           // m-groups (16 batch rows each) -- independent recurrences
#define SUBS 32            // n-CTAs per group
#define SCAN_CTAS (GROUPS * SUBS)   // 128
#define SCAN_NT 16         // hidden columns per CTA
#define MROWS 16           // batch rows per group
#define HSTRIDE 520        // 512 + 8 pad halves (16B-aligned rows, conflict-free LDSM)

// ---------------- scratch (device globals; no allocation allowed) ----------
__device__ __align__(16) __nv_bfloat16 g_hh[2][NB * HH];  // h hi, double buffered
__device__ __align__(16) __nv_bfloat16 g_hl[2][NB * HH];  // h lo
__device__ __align__(128) unsigned g_flag[GROUPS][SUBS];  // per-CTA publish flags

// ---------------- helpers --------------------------------------------------
__device__ __forceinline__ void split2(float v, __nv_bfloat16 &hi, __nv_bfloat16 &lo) {
    hi = __float2bfloat16(v);
    lo = __float2bfloat16(v - __bfloat162float(hi));
}

__device__ __forceinline__ void mma4(float *c, unsigned a0, unsigned a1, unsigned a2,
                                     unsigned a3, unsigned b0, unsigned b1) {
    asm volatile(
        "mma.sync.aligned.m16n8k16.row.col.f32.bf16.bf16.f32 "
        "{%0,%1,%2,%3}, {%4,%5,%6,%7}, {%8,%9}, {%0,%1,%2,%3};\n"
        : "+f"(c[0]), "+f"(c[1]), "+f"(c[2]), "+f"(c[3])
        : "r"(a0), "r"(a1), "r"(a2), "r"(a3), "r"(b0), "r"(b1));
}

__device__ __forceinline__ void ldsm_x4(unsigned &r0, unsigned &r1, unsigned &r2,
                                        unsigned &r3, unsigned addr) {
    asm volatile("ldmatrix.sync.aligned.m8n8.x4.shared.b16 {%0,%1,%2,%3}, [%4];"
                 : "=r"(r0), "=r"(r1), "=r"(r2), "=r"(r3)
                 : "r"(addr));
}

__device__ __forceinline__ void cp16(void *dst_smem, const void *src) {
    unsigned d = (unsigned)__cvta_generic_to_shared(dst_smem);
    asm volatile("cp.async.cg.shared.global [%0], [%1], 16;" :: "r"(d), "l"(src));
}

__device__ __forceinline__ float fast_tanh(float x) {
    float e = __expf(2.0f * x);
    return 1.0f - __fdividef(2.0f, e + 1.0f);
}

// ---------------- kernel 1: xWx = x @ Wx + b  -> out ------------------------
// CTA tile 128x64, BK=32, 256 threads. Fragments via ldmatrix.
__global__ __launch_bounds__(256) void gemm_xwx_kernel(
    const float *__restrict__ x, const float *__restrict__ Wx,
    const float *__restrict__ b, float *__restrict__ out) {

    __shared__ __align__(16) __nv_bfloat16 Ah[128 * 40];
    __shared__ __align__(16) __nv_bfloat16 Al[128 * 40];
    __shared__ __align__(16) __nv_bfloat16 Bh[64 * 40];
    __shared__ __align__(16) __nv_bfloat16 Bl[64 * 40];

    const int tid  = threadIdx.x;
    const int warp = tid >> 5;
    const int lane = tid & 31;
    const int g    = lane >> 2;
    const int tg   = lane & 3;
    const int wm   = warp >> 1;
    const int wn   = warp & 1;
    const int row0 = blockIdx.x * 128;
    const int col0 = blockIdx.y * 64;

    // ldmatrix lane addresses (tile-local, constant over k0)
    const int quad = lane >> 3, lrow = lane & 7;
    unsigned aHaddr[2], aLaddr[2], bAddr[4];
#pragma unroll
    for (int mt = 0; mt < 2; mt++) {
        int r = wm * 32 + mt * 16 + (quad & 1) * 8 + lrow;
        int off = r * 40 + (quad >> 1) * 8;
        aHaddr[mt] = (unsigned)__cvta_generic_to_shared(Ah + off);
        aLaddr[mt] = (unsigned)__cvta_generic_to_shared(Al + off);
    }
#pragma unroll
    for (int nt = 0; nt < 4; nt++) {
        int r = wn * 32 + nt * 8 + lrow;
        const __nv_bfloat16 *base = (quad < 2) ? Bh : Bl;
        bAddr[nt] = (unsigned)__cvta_generic_to_shared(base + r * 40 + (quad & 1) * 8);
    }

    float acc[2][4][4];
#pragma unroll
    for (int mt = 0; mt < 2; mt++)
#pragma unroll
        for (int nt = 0; nt < 4; nt++)
#pragma unroll
            for (int i = 0; i < 4; i++) acc[mt][nt][i] = 0.0f;

    for (int k0 = 0; k0 < DD; k0 += 32) {
        __syncthreads();
#pragma unroll
        for (int i = 0; i < 16; i++) {
            int idx = tid + i * 256;
            int r = idx >> 5, c = idx & 31;
            float v = x[(size_t)(row0 + r) * DD + k0 + c];
            __nv_bfloat16 hi, lo; split2(v, hi, lo);
            Ah[r * 40 + c] = hi; Al[r * 40 + c] = lo;
        }
#pragma unroll
        for (int i = 0; i < 8; i++) {
            int idx = tid + i * 256;
            int nn = idx & 63, kk = idx >> 6;
            float v = Wx[(size_t)(k0 + kk) * HH + col0 + nn];
            __nv_bfloat16 hi, lo; split2(v, hi, lo);
            Bh[nn * 40 + kk] = hi; Bl[nn * 40 + kk] = lo;
        }
        __syncthreads();

#pragma unroll
        for (int ks = 0; ks < 2; ks++) {
            const unsigned off = ks * 32;   // 16 halves = 32 bytes
            unsigned bfr[4][4];
#pragma unroll
            for (int nt = 0; nt < 4; nt++)
                ldsm_x4(bfr[nt][0], bfr[nt][1], bfr[nt][2], bfr[nt][3], bAddr[nt] + off);
#pragma unroll
            for (int mt = 0; mt < 2; mt++) {
                unsigned a0, a1, a2, a3, l0, l1, l2, l3;
                ldsm_x4(a0, a1, a2, a3, aHaddr[mt] + off);
                ldsm_x4(l0, l1, l2, l3, aLaddr[mt] + off);
#pragma unroll
                for (int nt = 0; nt < 4; nt++) {
                    mma4(acc[mt][nt], a0, a1, a2, a3, bfr[nt][0], bfr[nt][1]);
                    mma4(acc[mt][nt], a0, a1, a2, a3, bfr[nt][2], bfr[nt][3]);
                    mma4(acc[mt][nt], l0, l1, l2, l3, bfr[nt][0], bfr[nt][1]);
                }
            }
        }
    }

#pragma unroll
    for (int mt = 0; mt < 2; mt++)
#pragma unroll
        for (int nt = 0; nt < 4; nt++) {
            int r = row0 + wm * 32 + mt * 16 + g;
            int c = col0 + wn * 32 + nt * 8 + tg * 2;
            float b0 = b[c], b1 = b[c + 1];
            out[(size_t)r * HH + c]           = acc[mt][nt][0] + b0;
            out[(size_t)r * HH + c + 1]       = acc[mt][nt][1] + b1;
            out[(size_t)(r + 8) * HH + c]     = acc[mt][nt][2] + b0;
            out[(size_t)(r + 8) * HH + c + 1] = acc[mt][nt][3] + b1;
        }
}

// ---------------- flag reset (per graph replay determinism) -----------------
__global__ void reset_bar_kernel() {
    int i = threadIdx.x;
    if (i < GROUPS * SUBS) ((unsigned *)g_flag)[i] = 0;
}

// ---------------- kernel 2: persistent recurrent scan -----------------------
// 128 CTAs = 4 independent m-groups (16 batch rows) x 32 n-CTAs (16 cols).
// 8 warps: 4 K-quarters x 2 n-tiles. Sync = distributed per-CTA release flags.
__global__ __launch_bounds__(256) void rnn_scan_kernel(
    const float *__restrict__ h0, const float *__restrict__ Wh,
    float *__restrict__ out) {

    extern __shared__ __nv_bfloat16 smem[];
    __nv_bfloat16 *Hh  = smem;                        // 16 x 520
    __nv_bfloat16 *Hl  = Hh + MROWS * HSTRIDE;        // 16 x 520
    __nv_bfloat16 *Wsh = Hl + MROWS * HSTRIDE;        // 16 x 520
    __nv_bfloat16 *Wsl = Wsh + SCAN_NT * HSTRIDE;     // 16 x 520
    __shared__ float redbuf[6 * 128];                 // 3 k-partials x 2 ntiles

    const int tid   = threadIdx.x;
    const int warp  = tid >> 5;
    const int lane  = tid & 31;
    const int g     = lane >> 2;
    const int tg    = lane & 3;
    const int group = blockIdx.x >> 5;
    const int sub   = blockIdx.x & 31;
    const int cb    = sub * SCAN_NT;
    const int rbase = group * MROWS;
    const int kq    = warp >> 1;        // K-quarter 0..3
    const int ntile = warp & 1;         // n8 tile 0..1
    const int kb    = kq * 128;         // K offset in elements

    // resident Wh slice: Wsh[n][k] = Wh[k][cb+n], split hi/lo
    for (int idx = tid; idx < HH * SCAN_NT; idx += 256) {
        int n = idx & (SCAN_NT - 1), k = idx >> 4;
        float v = Wh[(size_t)k * HH + cb + n];
        __nv_bfloat16 hi, lo; split2(v, hi, lo);
        Wsh[n * HSTRIDE + k] = hi; Wsl[n * HSTRIDE + k] = lo;
    }

    // ldmatrix lane addresses (constant across steps)
    const int quad = lane >> 3, lrow = lane & 7;
    const int aRow = (quad & 1) * 8 + lrow;
    const int aCol = kb + (quad >> 1) * 8;
    const unsigned addrAh = (unsigned)__cvta_generic_to_shared(Hh + aRow * HSTRIDE + aCol);
    const unsigned addrAl = (unsigned)__cvta_generic_to_shared(Hl + aRow * HSTRIDE + aCol);
    const __nv_bfloat16 *bbase = (quad < 2) ? Wsh : Wsl;
    const unsigned addrB = (unsigned)__cvta_generic_to_shared(
        bbase + (ntile * 8 + lrow) * HSTRIDE + kb + (quad & 1) * 8);

    const int ccol = cb + ntile * 8 + tg * 2;
    const int m0 = rbase + g, m1 = rbase + g + 8;

    for (int t = 0; t < TT; t++) {
        // ---- prefetch xwx (independent of recurrence dataflow) ----
        float2 xw0, xw1;
        if (kq == 0) {
            xw0 = *(const float2 *)&out[((size_t)m0 * TT + t) * HH + ccol];
            xw1 = *(const float2 *)&out[((size_t)m1 * TT + t) * HH + ccol];
        }

        if (t == 0) {
            // stage h0 directly with split conversion
#pragma unroll
            for (int i = 0; i < 8; i++) {
                int idx = tid + i * 256;          // 2048 float4
                int r = idx >> 7, c4i = idx & 127;
                float4 v = ((const float4 *)(h0 + (size_t)(rbase + r) * HH))[c4i];
                __nv_bfloat16 hx, lx, hy, ly, hz, lz, hw, lw;
                split2(v.x, hx, lx); split2(v.y, hy, ly);
                split2(v.z, hz, lz); split2(v.w, hw, lw);
                __nv_bfloat162 ph01 = {hx, hy}, ph23 = {hz, hw};
                __nv_bfloat162 pl01 = {lx, ly}, pl23 = {lz, lw};
                uint2 uh = {*(unsigned *)&ph01, *(unsigned *)&ph23};
                uint2 ul = {*(unsigned *)&pl01, *(unsigned *)&pl23};
                ((uint2 *)(Hh + r * HSTRIDE))[c4i] = uh;
                ((uint2 *)(Hl + r * HSTRIDE))[c4i] = ul;
            }
        } else {
            // wait: all 32 producers of this group have published h_{t-1}
            if (warp == 0) {
                unsigned *fp = &g_flag[group][lane];
                unsigned v;
                do {
                    asm volatile("ld.acquire.gpu.global.u32 %0, [%1];"
                                 : "=r"(v) : "l"(fp) : "memory");
                } while (v < (unsigned)t);
            }
            __syncthreads();   // (A) release other warps to stage

            const __nv_bfloat16 *sH = g_hh[(t - 1) & 1] + (size_t)rbase * HH;
            const __nv_bfloat16 *sL = g_hl[(t - 1) & 1] + (size_t)rbase * HH;
#pragma unroll
            for (int i = 0; i < 4; i++) {
                int idx = tid + i * 256;          // 1024 x 16B
                int r = idx >> 6, c = idx & 63;
                cp16(Hh + r * HSTRIDE + c * 8, sH + r * HH + c * 8);
            }
            asm volatile("cp.async.commit_group;");
#pragma unroll
            for (int i = 0; i < 4; i++) {
                int idx = tid + i * 256;
                int r = idx >> 6, c = idx & 63;
                cp16(Hl + r * HSTRIDE + c * 8, sL + r * HH + c * 8);
            }
            asm volatile("cp.async.commit_group;");
            asm volatile("cp.async.wait_group 1;");   // Hh ready
        }
        __syncthreads();   // (B)

        // ---- pass 1: Ah*Bh + Ah*Bl (needs only Hh); save B-hi frags ----
        float c4[4] = {0.f, 0.f, 0.f, 0.f};
        unsigned sb0[8], sb1[8];
#pragma unroll
        for (int kk = 0; kk < 8; kk++) {
            const unsigned off = kk * 32;
            unsigned a0, a1, a2, a3, b0, b1, b2, b3;
            ldsm_x4(a0, a1, a2, a3, addrAh + off);
            ldsm_x4(b0, b1, b2, b3, addrB + off);
            sb0[kk] = b0; sb1[kk] = b1;
            mma4(c4, a0, a1, a2, a3, b0, b1);
            mma4(c4, a0, a1, a2, a3, b2, b3);
        }

        asm volatile("cp.async.wait_group 0;");       // Hl ready
        __syncthreads();   // (C)

        // ---- pass 2: Al*Bh (reuse saved B-hi fragments) ----
#pragma unroll
        for (int kk = 0; kk < 8; kk++) {
            const unsigned off = kk * 32;
            unsigned l0, l1, l2, l3;
            ldsm_x4(l0, l1, l2, l3, addrAl + off);
            mma4(c4, l0, l1, l2, l3, sb0[kk], sb1[kk]);
        }

        // ---- cross-K reduction ----
        if (kq > 0) {
            float *dst = &redbuf[((kq - 1) * 2 + ntile) * 128 + lane * 4];
            dst[0] = c4[0]; dst[1] = c4[1]; dst[2] = c4[2]; dst[3] = c4[3];
        }
        __syncthreads();   // (D)

        // ---- epilogue (warps 0-1) ----
        if (kq == 0) {
            float v0 = c4[0], v1 = c4[1], v2 = c4[2], v3 = c4[3];
#pragma unroll
            for (int j = 0; j < 3; j++) {
                const float *src = &redbuf[(j * 2 + ntile) * 128 + lane * 4];
                v0 += src[0]; v1 += src[1]; v2 += src[2]; v3 += src[3];
            }
            v0 += xw0.x; v1 += xw0.y; v2 += xw1.x; v3 += xw1.y;
            float h0v = fast_tanh(v0), h1v = fast_tanh(v1);
            float h2v = fast_tanh(v2), h3v = fast_tanh(v3);

            // publish h first (release set is just these stores)
            const int wb = t & 1;
            __nv_bfloat16 hi, lo;
            __nv_bfloat162 ph, pl;
            split2(h0v, hi, lo); ph.x = hi; pl.x = lo;
            split2(h1v, hi, lo); ph.y = hi; pl.y = lo;
            *(unsigned *)&g_hh[wb][m0 * HH + ccol] = *(unsigned *)&ph;
            *(unsigned *)&g_hl[wb][m0 * HH + ccol] = *(unsigned *)&pl;
            split2(h2v, hi, lo); ph.x = hi; pl.x = lo;
            split2(h3v, hi, lo); ph.y = hi; pl.y = lo;
            *(unsigned *)&g_hh[wb][m1 * HH + ccol] = *(unsigned *)&ph;
            *(unsigned *)&g_hl[wb][m1 * HH + ccol] = *(unsigned *)&pl;

            asm volatile("bar.sync 1, 64;" ::: "memory");  // warps 0-1 h-stores done
            if (tid == 0 && t < TT - 1) {
                asm volatile("st.release.gpu.global.u32 [%0], %1;"
                             :: "l"(&g_flag[group][sub]), "r"((unsigned)(t + 1)) : "memory");
            }

            // final outputs, off the release path
            *(float2 *)&out[((size_t)m0 * TT + t) * HH + ccol] = make_float2(h0v, h1v);
            *(float2 *)&out[((size_t)m1 * TT + t) * HH + ccol] = make_float2(h2v, h3v);
        }
    }
}

// ---------------- launch ----------------------------------------------------
extern "C" void kernel_launch(void *const *d_in, const int *in_sizes, int n_in,
                              void *d_out, int out_size) {
    const float *x  = (const float *)d_in[0];   // (64, 512, 512)
    const float *h0 = (const float *)d_in[1];   // (64, 512)
    const float *Wx = (const float *)d_in[2];   // (512, 512)
    const float *Wh = (const float *)d_in[3];   // (512, 512)
    const float *b  = (const float *)d_in[4];   // (512,)
    float *out = (float *)d_out;                // (64, 512, 512)

    const int scan_smem =
        (2 * MROWS * HSTRIDE + 2 * SCAN_NT * HSTRIDE) * (int)sizeof(__nv_bfloat16);
    cudaFuncSetAttribute(rnn_scan_kernel,
                         cudaFuncAttributeMaxDynamicSharedMemorySize, scan_smem);

    dim3 grid1(NB * TT / 128, HH / 64);
    gemm_xwx_kernel<<<grid1, 256>>>(x, Wx, b, out);
    reset_bar_kernel<<<1, 128>>>();
    rnn_scan_kernel<<<SCAN_CTAS, 256, scan_smem>>>(h0, Wh, out);
}

// round 5
// speedup vs baseline: 1.6414x; 1.6414x over previous
#include <cuda_runtime.h>
#include <cuda_bf16.h>

#define NB 64      // batch
#define TT 512     // timesteps
#define DD 512     // input size
#define HH 512     // hidden size

#define GROUPS 4           // m-groups (16 batch rows each) -- independent recurrences
#define SUBS 32            // n-CTAs per group
#define SCAN_CTAS (GROUPS * SUBS)   // 128
#define SCAN_NT 16         // hidden columns per CTA
#define MROWS 16           // batch rows per group
#define HSTRIDE 520        // 512 + 8 pad halves (16B-aligned rows, conflict-free LDSM)

// ---------------- scratch (device globals; no allocation allowed) ----------
__device__ __align__(16) __nv_bfloat16 g_hh[2][NB * HH];  // h hi, double buffered
__device__ __align__(16) __nv_bfloat16 g_hl[2][NB * HH];  // h lo
__device__ __align__(128) unsigned g_cnt[GROUPS * 32];    // monotonic arrival counters (128B apart)

// ---------------- helpers --------------------------------------------------
__device__ __forceinline__ void split2(float v, __nv_bfloat16 &hi, __nv_bfloat16 &lo) {
    hi = __float2bfloat16(v);
    lo = __float2bfloat16(v - __bfloat162float(hi));
}

__device__ __forceinline__ void mma4(float *c, unsigned a0, unsigned a1, unsigned a2,
                                     unsigned a3, unsigned b0, unsigned b1) {
    asm volatile(
        "mma.sync.aligned.m16n8k16.row.col.f32.bf16.bf16.f32 "
        "{%0,%1,%2,%3}, {%4,%5,%6,%7}, {%8,%9}, {%0,%1,%2,%3};\n"
        : "+f"(c[0]), "+f"(c[1]), "+f"(c[2]), "+f"(c[3])
        : "r"(a0), "r"(a1), "r"(a2), "r"(a3), "r"(b0), "r"(b1));
}

__device__ __forceinline__ void ldsm_x4(unsigned &r0, unsigned &r1, unsigned &r2,
                                        unsigned &r3, unsigned addr) {
    asm volatile("ldmatrix.sync.aligned.m8n8.x4.shared.b16 {%0,%1,%2,%3}, [%4];"
                 : "=r"(r0), "=r"(r1), "=r"(r2), "=r"(r3)
                 : "r"(addr));
}

__device__ __forceinline__ void cp16(void *dst_smem, const void *src) {
    unsigned d = (unsigned)__cvta_generic_to_shared(dst_smem);
    asm volatile("cp.async.cg.shared.global [%0], [%1], 16;" :: "r"(d), "l"(src));
}

__device__ __forceinline__ float fast_tanh(float x) {
    float e = __expf(2.0f * x);
    return 1.0f - __fdividef(2.0f, e + 1.0f);
}

// ---------------- kernel 1: xWx = x @ Wx + b  -> out ------------------------
// CTA tile 128x64, BK=32, 256 threads. Fragments via ldmatrix.
__global__ __launch_bounds__(256) void gemm_xwx_kernel(
    const float *__restrict__ x, const float *__restrict__ Wx,
    const float *__restrict__ b, float *__restrict__ out) {

    __shared__ __align__(16) __nv_bfloat16 Ah[128 * 40];
    __shared__ __align__(16) __nv_bfloat16 Al[128 * 40];
    __shared__ __align__(16) __nv_bfloat16 Bh[64 * 40];
    __shared__ __align__(16) __nv_bfloat16 Bl[64 * 40];

    const int tid  = threadIdx.x;
    const int warp = tid >> 5;
    const int lane = tid & 31;
    const int g    = lane >> 2;
    const int tg   = lane & 3;
    const int wm   = warp >> 1;
    const int wn   = warp & 1;
    const int row0 = blockIdx.x * 128;
    const int col0 = blockIdx.y * 64;

    const int quad = lane >> 3, lrow = lane & 7;
    unsigned aHaddr[2], aLaddr[2], bAddr[4];
#pragma unroll
    for (int mt = 0; mt < 2; mt++) {
        int r = wm * 32 + mt * 16 + (quad & 1) * 8 + lrow;
        int off = r * 40 + (quad >> 1) * 8;
        aHaddr[mt] = (unsigned)__cvta_generic_to_shared(Ah + off);
        aLaddr[mt] = (unsigned)__cvta_generic_to_shared(Al + off);
    }
#pragma unroll
    for (int nt = 0; nt < 4; nt++) {
        int r = wn * 32 + nt * 8 + lrow;
        const __nv_bfloat16 *base = (quad < 2) ? Bh : Bl;
        bAddr[nt] = (unsigned)__cvta_generic_to_shared(base + r * 40 + (quad & 1) * 8);
    }

    float acc[2][4][4];
#pragma unroll
    for (int mt = 0; mt < 2; mt++)
#pragma unroll
        for (int nt = 0; nt < 4; nt++)
#pragma unroll
            for (int i = 0; i < 4; i++) acc[mt][nt][i] = 0.0f;

    for (int k0 = 0; k0 < DD; k0 += 32) {
        __syncthreads();
#pragma unroll
        for (int i = 0; i < 16; i++) {
            int idx = tid + i * 256;
            int r = idx >> 5, c = idx & 31;
            float v = x[(size_t)(row0 + r) * DD + k0 + c];
            __nv_bfloat16 hi, lo; split2(v, hi, lo);
            Ah[r * 40 + c] = hi; Al[r * 40 + c] = lo;
        }
#pragma unroll
        for (int i = 0; i < 8; i++) {
            int idx = tid + i * 256;
            int nn = idx & 63, kk = idx >> 6;
            float v = Wx[(size_t)(k0 + kk) * HH + col0 + nn];
            __nv_bfloat16 hi, lo; split2(v, hi, lo);
            Bh[nn * 40 + kk] = hi; Bl[nn * 40 + kk] = lo;
        }
        __syncthreads();

#pragma unroll
        for (int ks = 0; ks < 2; ks++) {
            const unsigned off = ks * 32;   // 16 halves = 32 bytes
            unsigned bfr[4][4];
#pragma unroll
            for (int nt = 0; nt < 4; nt++)
                ldsm_x4(bfr[nt][0], bfr[nt][1], bfr[nt][2], bfr[nt][3], bAddr[nt] + off);
#pragma unroll
            for (int mt = 0; mt < 2; mt++) {
                unsigned a0, a1, a2, a3, l0, l1, l2, l3;
                ldsm_x4(a0, a1, a2, a3, aHaddr[mt] + off);
                ldsm_x4(l0, l1, l2, l3, aLaddr[mt] + off);
#pragma unroll
                for (int nt = 0; nt < 4; nt++) {
                    mma4(acc[mt][nt], a0, a1, a2, a3, bfr[nt][0], bfr[nt][1]);
                    mma4(acc[mt][nt], a0, a1, a2, a3, bfr[nt][2], bfr[nt][3]);
                    mma4(acc[mt][nt], l0, l1, l2, l3, bfr[nt][0], bfr[nt][1]);
                }
            }
        }
    }

#pragma unroll
    for (int mt = 0; mt < 2; mt++)
#pragma unroll
        for (int nt = 0; nt < 4; nt++) {
            int r = row0 + wm * 32 + mt * 16 + g;
            int c = col0 + wn * 32 + nt * 8 + tg * 2;
            float b0 = b[c], b1 = b[c + 1];
            out[(size_t)r * HH + c]           = acc[mt][nt][0] + b0;
            out[(size_t)r * HH + c + 1]       = acc[mt][nt][1] + b1;
            out[(size_t)(r + 8) * HH + c]     = acc[mt][nt][2] + b0;
            out[(size_t)(r + 8) * HH + c + 1] = acc[mt][nt][3] + b1;
        }
}

// ---------------- counter reset (per graph replay determinism) --------------
__global__ void reset_bar_kernel() {
    int i = threadIdx.x;
    if (i < GROUPS * 32) g_cnt[i] = 0;
}

// ---------------- kernel 2: persistent recurrent scan -----------------------
// 128 CTAs = 4 independent m-groups (16 batch rows) x 32 n-CTAs (16 cols).
// 8 warps: 4 K-quarters x 2 n-tiles. Sync: fire-and-forget red.release on a
// monotonic per-group counter; consumers poll counter >= 32*t (no winner hop).
__global__ __launch_bounds__(256) void rnn_scan_kernel(
    const float *__restrict__ h0, const float *__restrict__ Wh,
    float *__restrict__ out) {

    extern __shared__ __nv_bfloat16 smem[];
    __nv_bfloat16 *Hh  = smem;                        // 16 x 520
    __nv_bfloat16 *Hl  = Hh + MROWS * HSTRIDE;        // 16 x 520
    __nv_bfloat16 *Wsh = Hl + MROWS * HSTRIDE;        // 16 x 520
    __nv_bfloat16 *Wsl = Wsh + SCAN_NT * HSTRIDE;     // 16 x 520
    __shared__ float redbuf[6 * 128];                 // 3 k-partials x 2 ntiles

    const int tid   = threadIdx.x;
    const int warp  = tid >> 5;
    const int lane  = tid & 31;
    const int g     = lane >> 2;
    const int tg    = lane & 3;
    const int group = blockIdx.x >> 5;
    const int sub   = blockIdx.x & 31;
    const int cb    = sub * SCAN_NT;
    const int rbase = group * MROWS;
    const int kq    = warp >> 1;        // K-quarter 0..3
    const int ntile = warp & 1;         // n8 tile 0..1
    const int kb    = kq * 128;         // K offset in elements

    unsigned *cntp = &g_cnt[group * 32];

    // resident Wh slice: Wsh[n][k] = Wh[k][cb+n], split hi/lo
    for (int idx = tid; idx < HH * SCAN_NT; idx += 256) {
        int n = idx & (SCAN_NT - 1), k = idx >> 4;
        float v = Wh[(size_t)k * HH + cb + n];
        __nv_bfloat16 hi, lo; split2(v, hi, lo);
        Wsh[n * HSTRIDE + k] = hi; Wsl[n * HSTRIDE + k] = lo;
    }

    // ldmatrix lane addresses (constant across steps)
    const int quad = lane >> 3, lrow = lane & 7;
    const int aRow = (quad & 1) * 8 + lrow;
    const int aCol = kb + (quad >> 1) * 8;
    const unsigned addrAh = (unsigned)__cvta_generic_to_shared(Hh + aRow * HSTRIDE + aCol);
    const unsigned addrAl = (unsigned)__cvta_generic_to_shared(Hl + aRow * HSTRIDE + aCol);
    const __nv_bfloat16 *bbase = (quad < 2) ? Wsh : Wsl;
    const unsigned addrB = (unsigned)__cvta_generic_to_shared(
        bbase + (ntile * 8 + lrow) * HSTRIDE + kb + (quad & 1) * 8);

    const int ccol = cb + ntile * 8 + tg * 2;
    const int m0 = rbase + g, m1 = rbase + g + 8;

    for (int t = 0; t < TT; t++) {
        // ---- prefetch xwx (independent of recurrence dataflow) ----
        float2 xw0, xw1;
        if (kq == 0) {
            xw0 = *(const float2 *)&out[((size_t)m0 * TT + t) * HH + ccol];
            xw1 = *(const float2 *)&out[((size_t)m1 * TT + t) * HH + ccol];
        }

        if (t == 0) {
            // stage h0 directly with split conversion
#pragma unroll
            for (int i = 0; i < 8; i++) {
                int idx = tid + i * 256;          // 2048 float4
                int r = idx >> 7, c4i = idx & 127;
                float4 v = ((const float4 *)(h0 + (size_t)(rbase + r) * HH))[c4i];
                __nv_bfloat16 hx, lx, hy, ly, hz, lz, hw, lw;
                split2(v.x, hx, lx); split2(v.y, hy, ly);
                split2(v.z, hz, lz); split2(v.w, hw, lw);
                __nv_bfloat162 ph01 = {hx, hy}, ph23 = {hz, hw};
                __nv_bfloat162 pl01 = {lx, ly}, pl23 = {lz, lw};
                uint2 uh = {*(unsigned *)&ph01, *(unsigned *)&ph23};
                uint2 ul = {*(unsigned *)&pl01, *(unsigned *)&pl23};
                ((uint2 *)(Hh + r * HSTRIDE))[c4i] = uh;
                ((uint2 *)(Hl + r * HSTRIDE))[c4i] = ul;
            }
            __syncthreads();
        } else {
            // wait: all 32 CTAs of this group completed step t-1
            if (tid == 0) {
                const unsigned target = (unsigned)(SUBS * t);
                unsigned v;
                do {
                    asm volatile("ld.relaxed.gpu.global.u32 %0, [%1];"
                                 : "=r"(v) : "l"(cntp) : "memory");
                } while (v < target);
                asm volatile("ld.acquire.gpu.global.u32 %0, [%1];"
                             : "=r"(v) : "l"(cntp) : "memory");
            }
            __syncthreads();

            const __nv_bfloat16 *sH = g_hh[(t - 1) & 1] + (size_t)rbase * HH;
            const __nv_bfloat16 *sL = g_hl[(t - 1) & 1] + (size_t)rbase * HH;
#pragma unroll
            for (int i = 0; i < 4; i++) {
                int idx = tid + i * 256;          // 1024 x 16B per buffer
                int r = idx >> 6, c = idx & 63;
                cp16(Hh + r * HSTRIDE + c * 8, sH + r * HH + c * 8);
            }
#pragma unroll
            for (int i = 0; i < 4; i++) {
                int idx = tid + i * 256;
                int r = idx >> 6, c = idx & 63;
                cp16(Hl + r * HSTRIDE + c * 8, sL + r * HH + c * 8);
            }
            asm volatile("cp.async.commit_group;");
            asm volatile("cp.async.wait_group 0;");
            __syncthreads();
        }

        // ---- k-loop: 8 x k16 per warp, split-bf16 3-term ----
        float c4[4] = {0.f, 0.f, 0.f, 0.f};
#pragma unroll
        for (int kk = 0; kk < 8; kk++) {
            const unsigned off = kk * 32;  // 16 halves = 32 bytes
            unsigned a0, a1, a2, a3, l0, l1, l2, l3, b0, b1, b2, b3;
            ldsm_x4(a0, a1, a2, a3, addrAh + off);
            ldsm_x4(l0, l1, l2, l3, addrAl + off);
            ldsm_x4(b0, b1, b2, b3, addrB + off);
            mma4(c4, a0, a1, a2, a3, b0, b1);   // Ah*Bh
            mma4(c4, a0, a1, a2, a3, b2, b3);   // Ah*Bl
            mma4(c4, l0, l1, l2, l3, b0, b1);   // Al*Bh
        }

        // ---- cross-K reduction (kq 1..3 -> redbuf) ----
        if (kq > 0) {
            float *dst = &redbuf[((kq - 1) * 2 + ntile) * 128 + lane * 4];
            dst[0] = c4[0]; dst[1] = c4[1]; dst[2] = c4[2]; dst[3] = c4[3];
        }
        __syncthreads();

        // ---- epilogue (warps 0-1) ----
        if (kq == 0) {
            float v0 = c4[0], v1 = c4[1], v2 = c4[2], v3 = c4[3];
#pragma unroll
            for (int j = 0; j < 3; j++) {
                const float *src = &redbuf[(j * 2 + ntile) * 128 + lane * 4];
                v0 += src[0]; v1 += src[1]; v2 += src[2]; v3 += src[3];
            }
            v0 += xw0.x; v1 += xw0.y; v2 += xw1.x; v3 += xw1.y;
            float h0v = fast_tanh(v0), h1v = fast_tanh(v1);
            float h2v = fast_tanh(v2), h3v = fast_tanh(v3);

            // publish h first (release set is just these stores)
            const int wb = t & 1;
            __nv_bfloat16 hi, lo;
            __nv_bfloat162 ph, pl;
            split2(h0v, hi, lo); ph.x = hi; pl.x = lo;
            split2(h1v, hi, lo); ph.y = hi; pl.y = lo;
            *(unsigned *)&g_hh[wb][m0 * HH + ccol] = *(unsigned *)&ph;
            *(unsigned *)&g_hl[wb][m0 * HH + ccol] = *(unsigned *)&pl;
            split2(h2v, hi, lo); ph.x = hi; pl.x = lo;
            split2(h3v, hi, lo); ph.y = hi; pl.y = lo;
            *(unsigned *)&g_hh[wb][m1 * HH + ccol] = *(unsigned *)&ph;
            *(unsigned *)&g_hl[wb][m1 * HH + ccol] = *(unsigned *)&pl;

            asm volatile("bar.sync 1, 64;" ::: "memory");  // warps 0-1 h-stores done
            if (tid == 0 && t < TT - 1) {
                // fire-and-forget arrival: no return value, no serial round trip
                asm volatile("red.release.gpu.global.add.u32 [%0], %1;"
                             :: "l"(cntp), "r"(1u) : "memory");
            }

            // final outputs, off the release path (overlap next-step wait)
            *(float2 *)&out[((size_t)m0 * TT + t) * HH + ccol] = make_float2(h0v, h1v);
            *(float2 *)&out[((size_t)m1 * TT + t) * HH + ccol] = make_float2(h2v, h3v);
        }
    }
}

// ---------------- launch ----------------------------------------------------
extern "C" void kernel_launch(void *const *d_in, const int *in_sizes, int n_in,
                              void *d_out, int out_size) {
    const float *x  = (const float *)d_in[0];   // (64, 512, 512)
    const float *h0 = (const float *)d_in[1];   // (64, 512)
    const float *Wx = (const float *)d_in[2];   // (512, 512)
    const float *Wh = (const float *)d_in[3];   // (512, 512)
    const float *b  = (const float *)d_in[4];   // (512,)
    float *out = (float *)d_out;                // (64, 512, 512)

    const int scan_smem =
        (2 * MROWS * HSTRIDE + 2 * SCAN_NT * HSTRIDE) * (int)sizeof(__nv_bfloat16);
    cudaFuncSetAttribute(rnn_scan_kernel,
                         cudaFuncAttributeMaxDynamicSharedMemorySize, scan_smem);

    dim3 grid1(NB * TT / 128, HH / 64);
    gemm_xwx_kernel<<<grid1, 256>>>(x, Wx, b, out);
    reset_bar_kernel<<<1, 128>>>();
    rnn_scan_kernel<<<SCAN_CTAS, 256, scan_smem>>>(h0, Wh, out);
}